// round 8
// baseline (speedup 1.0000x reference)
#include <cuda_runtime.h>
#include <math.h>
#include <stdint.h>

// Problem constants
#define BB 4
#define NN 2048
#define DD 1024
#define HH 16
#define HD 64
#define MTOT (BB*NN)          // 8192
#define ATT_SCALE 0.125f

// ---------------- scratch (static device memory; no allocations) ------------
__device__ float d_cpc[4 * 64 * 64];          // 4 x (r1 x r2)
__device__ float d_T[4 * 64 * 1024];          // 4 x (r x D)   T = cp @ V
__device__ float d_Weff[4 * 1024 * 1024];     // folded weights q,k,v,proj
__device__ float d_q[MTOT * DD];
__device__ float d_k[MTOT * DD];
__device__ float d_v[MTOT * DD];
__device__ float d_x[MTOT * DD];              // attention output

// ---------------- packed f32x2 helpers (Blackwell base target) ---------------
typedef unsigned long long ull_t;

__device__ __forceinline__ ull_t fma2(ull_t a, ull_t b, ull_t c) {
    ull_t d;
    asm("fma.rn.f32x2 %0, %1, %2, %3;" : "=l"(d) : "l"(a), "l"(b), "l"(c));
    return d;
}
__device__ __forceinline__ ull_t mul2(ull_t a, ull_t b) {
    ull_t d;
    asm("mul.rn.f32x2 %0, %1, %2;" : "=l"(d) : "l"(a), "l"(b));
    return d;
}
__device__ __forceinline__ ull_t dup2(float x) {
    ull_t r;
    asm("mov.b64 %0, {%1, %1};" : "=l"(r) : "f"(x));
    return r;
}
__device__ __forceinline__ void unpack2(ull_t v, float& lo, float& hi) {
    asm("mov.b64 {%0, %1}, %2;" : "=f"(lo), "=f"(hi) : "l"(v));
}

// ---------------- prep kernels ----------------------------------------------
__global__ void cpc_kernel(const float* __restrict__ cpC,
                           const float* __restrict__ cpAtt) {
    int idx = blockIdx.x * 256 + threadIdx.x;       // 16384 total
    int f = idx >> 12;
    int rem = idx & 4095;                           // x*64+y
    const float* c = cpC + rem * 64;
    float s = 0.f;
#pragma unroll 8
    for (int r = 0; r < 64; r++) s += c[r] * cpAtt[r * 4 + f];
    d_cpc[f * 4096 + rem] = s;
}

__global__ void tmat_kernel(const float* __restrict__ Vw) {
    int idx = blockIdx.x * 256 + threadIdx.x;       // 262144 total
    int f = idx >> 16;
    int rem = idx & 65535;
    int x = rem >> 10;
    int d = rem & 1023;
    const float* cp = d_cpc + f * 4096 + x * 64;
    float s = 0.f;
#pragma unroll 8
    for (int y = 0; y < 64; y++) s += cp[y] * Vw[y * 1024 + d];
    d_T[idx] = s;
}

__global__ void weff_kernel(const float* __restrict__ Wq, const float* __restrict__ Wk,
                            const float* __restrict__ Wv, const float* __restrict__ Wp,
                            const float* __restrict__ U) {
    int idx = blockIdx.x * 256 + threadIdx.x;       // 4 * 1M total
    int f = idx >> 20;
    int rem = idx & 1048575;
    int i = rem >> 10;
    int d = rem & 1023;
    const float* W = (f == 0) ? Wq : (f == 1) ? Wk : (f == 2) ? Wv : Wp;
    const float* Tf = d_T + f * 65536;
    const float* Ur = U + i * 64;
    float s = W[rem];
#pragma unroll 8
    for (int x = 0; x < 64; x++) s += Ur[x] * Tf[x * 1024 + d];
    d_Weff[idx] = s;
}

// ---------------- SGEMM (batched over z): C[M x 1024] = A @ B (+bias) --------
// 128x128x8 tile, 256 threads, 8x8 microtile, double-buffered smem (R2-verified)
__global__ void __launch_bounds__(256, 2)
sgemm3_kernel(const float* __restrict__ A0, const float* __restrict__ A1,
              const float* __restrict__ A2,
              const float* __restrict__ Bw, const float* __restrict__ bias,
              float* __restrict__ C0, float* __restrict__ C1, float* __restrict__ C2) {
    const int K = 1024, Nn = 1024;
    __shared__ float As[2][8][132];   // transposed, padded
    __shared__ float Bs[2][8][128];

    int z = blockIdx.z;
    const float* A  = (z == 0) ? A0 : (z == 1) ? A1 : A2;
    float*       C  = (z == 0) ? C0 : (z == 1) ? C1 : C2;
    const float* Bm = Bw + (long)z * 1048576;

    int bx = blockIdx.x * 128;
    int by = blockIdx.y * 128;
    int tid = threadIdx.x;
    int tx = tid & 15;
    int ty = tid >> 4;

    int arow = tid >> 1;           // 0..127
    int acol = (tid & 1) * 4;      // 0 or 4
    int brow = tid >> 5;           // 0..7
    int bcol = (tid & 31) * 4;     // 0..124

    const float* Aptr = A + (long)(by + arow) * K + acol;
    const float* Bptr = Bm + (long)brow * Nn + bx + bcol;

    float acc[8][8];
#pragma unroll
    for (int i = 0; i < 8; i++)
#pragma unroll
        for (int j = 0; j < 8; j++) acc[i][j] = 0.f;

    // prologue: load slab 0 into buffer 0
    float4 aReg = *(const float4*)Aptr;
    float4 bReg = *(const float4*)Bptr;
    As[0][acol + 0][arow] = aReg.x;
    As[0][acol + 1][arow] = aReg.y;
    As[0][acol + 2][arow] = aReg.z;
    As[0][acol + 3][arow] = aReg.w;
    *(float4*)&Bs[0][brow][bcol] = bReg;
    __syncthreads();

    int cur = 0;
    for (int kt = 0; kt < K / 8; kt++) {
        if (kt + 1 < K / 8) {
            aReg = *(const float4*)(Aptr + (kt + 1) * 8);
            bReg = *(const float4*)(Bptr + (long)(kt + 1) * 8 * Nn);
        }

#pragma unroll
        for (int kk = 0; kk < 8; kk++) {
            float a0[4], a1[4], b0[4], b1[4];
            *(float4*)a0 = *(const float4*)&As[cur][kk][ty * 4];
            *(float4*)a1 = *(const float4*)&As[cur][kk][64 + ty * 4];
            *(float4*)b0 = *(const float4*)&Bs[cur][kk][tx * 4];
            *(float4*)b1 = *(const float4*)&Bs[cur][kk][64 + tx * 4];
#pragma unroll
            for (int i = 0; i < 4; i++)
#pragma unroll
                for (int j = 0; j < 4; j++) {
                    acc[i][j]         += a0[i] * b0[j];
                    acc[i][j + 4]     += a0[i] * b1[j];
                    acc[i + 4][j]     += a1[i] * b0[j];
                    acc[i + 4][j + 4] += a1[i] * b1[j];
                }
        }

        if (kt + 1 < K / 8) {
            int nxt = cur ^ 1;
            As[nxt][acol + 0][arow] = aReg.x;
            As[nxt][acol + 1][arow] = aReg.y;
            As[nxt][acol + 2][arow] = aReg.z;
            As[nxt][acol + 3][arow] = aReg.w;
            *(float4*)&Bs[nxt][brow][bcol] = bReg;
            __syncthreads();
            cur = nxt;
        }
    }

    // epilogue
#pragma unroll
    for (int hi = 0; hi < 2; hi++) {
#pragma unroll
        for (int i = 0; i < 4; i++) {
            int row = by + hi * 64 + ty * 4 + i;
            float* Crow = C + (long)row * Nn + bx;
#pragma unroll
            for (int hj = 0; hj < 2; hj++) {
                int col = hj * 64 + tx * 4;
                float4 r;
                r.x = acc[hi * 4 + i][hj * 4 + 0];
                r.y = acc[hi * 4 + i][hj * 4 + 1];
                r.z = acc[hi * 4 + i][hj * 4 + 2];
                r.w = acc[hi * 4 + i][hj * 4 + 3];
                if (bias) {
                    float4 bb = *(const float4*)(bias + bx + col);
                    r.x += bb.x; r.y += bb.y; r.z += bb.z; r.w += bb.w;
                }
                *(float4*)(Crow + col) = r;
            }
        }
    }
}

// ---------------- flash attention (f32x2-packed inner loops) ------------------
// dyn smem 64KB: Qs[64][64] @0 | Ks float[64][64] @16K (dead after S) |
//                P2 ull[64][64] @16K..48K | Vs[64][64] @48K
#define ATTN_SMEM 65536

__global__ void __launch_bounds__(256, 2)
attn_kernel(const float* __restrict__ q, const float* __restrict__ k,
            const float* __restrict__ v, float* __restrict__ o) {
    extern __shared__ char asmem[];
    float (*Qs)[64] = (float(*)[64])(asmem);                 // [d][i], pre-scaled
    float (*Ks)[64] = (float(*)[64])(asmem + 16384);         // [d][j]
    ull_t (*P2)[64] = (ull_t(*)[64])(asmem + 16384);         // dup pairs [i][j]
    float (*Vs)[64] = (float(*)[64])(asmem + 49152);         // [j][d]

    int b = blockIdx.z, h = blockIdx.y, qt = blockIdx.x;
    int tid = threadIdx.x;
    int tx = tid & 15, ty = tid >> 4;

    const long hoff = (long)h * HD;
    const float* qbase = q + ((long)(b * NN + qt * 64)) * DD + hoff;
    const float* kbase = k + ((long)b * NN) * DD + hoff;
    const float* vbase = v + ((long)b * NN) * DD + hoff;

    // load Q tile transposed, fold in ATT_SCALE
#pragma unroll
    for (int it = 0; it < 4; it++) {
        int fid = tid + 256 * it;
        int i = fid >> 4, d4 = (fid & 15) << 2;
        float4 val = *(const float4*)(qbase + (long)i * DD + d4);
        Qs[d4 + 0][i] = val.x * ATT_SCALE;
        Qs[d4 + 1][i] = val.y * ATT_SCALE;
        Qs[d4 + 2][i] = val.z * ATT_SCALE;
        Qs[d4 + 3][i] = val.w * ATT_SCALE;
    }

    float m_r[4], l_r[4];
    ull_t Oc2[4][2];
#pragma unroll
    for (int i = 0; i < 4; i++) {
        m_r[i] = -1e30f; l_r[i] = 0.f;
        Oc2[i][0] = 0ull; Oc2[i][1] = 0ull;
    }

    for (int kt = 0; kt < 32; kt++) {
        __syncthreads();   // P2/Vs from prev iter dead; Q visible on first iter
        const float* kb = kbase + (long)kt * 64 * DD;
        const float* vb = vbase + (long)kt * 64 * DD;
#pragma unroll
        for (int it = 0; it < 4; it++) {
            int fid = tid + 256 * it;
            int i = fid >> 4, d4 = (fid & 15) << 2;
            float4 kv = *(const float4*)(kb + (long)i * DD + d4);
            Ks[d4 + 0][i] = kv.x; Ks[d4 + 1][i] = kv.y;
            Ks[d4 + 2][i] = kv.z; Ks[d4 + 3][i] = kv.w;
            float4 vv = *(const float4*)(vb + (long)i * DD + d4);
            *(float4*)&Vs[i][d4] = vv;
        }
        __syncthreads();

        // S = (Q*scale) K^T : packed along i-pairs (Qs[d][.] contiguous)
        ull_t s2[2][4];
#pragma unroll
        for (int ip = 0; ip < 2; ip++)
#pragma unroll
            for (int j = 0; j < 4; j++) s2[ip][j] = 0ull;

        for (int d = 0; d < 64; d++) {
            ulonglong2 a2 = *(const ulonglong2*)&Qs[d][ty * 4];
            float4 bk = *(const float4*)&Ks[d][tx * 4];
            ull_t b0 = dup2(bk.x), b1 = dup2(bk.y);
            ull_t b2 = dup2(bk.z), b3 = dup2(bk.w);
            s2[0][0] = fma2(a2.x, b0, s2[0][0]);
            s2[0][1] = fma2(a2.x, b1, s2[0][1]);
            s2[0][2] = fma2(a2.x, b2, s2[0][2]);
            s2[0][3] = fma2(a2.x, b3, s2[0][3]);
            s2[1][0] = fma2(a2.y, b0, s2[1][0]);
            s2[1][1] = fma2(a2.y, b1, s2[1][1]);
            s2[1][2] = fma2(a2.y, b2, s2[1][2]);
            s2[1][3] = fma2(a2.y, b3, s2[1][3]);
        }

        float s[4][4];
#pragma unroll
        for (int j = 0; j < 4; j++) {
            unpack2(s2[0][j], s[0][j], s[1][j]);
            unpack2(s2[1][j], s[2][j], s[3][j]);
        }

        // online softmax: row stats across the 16 tx lanes
        float mnew[4], corr[4];
#pragma unroll
        for (int i = 0; i < 4; i++) {
            float rmax = fmaxf(fmaxf(s[i][0], s[i][1]), fmaxf(s[i][2], s[i][3]));
#pragma unroll
            for (int off = 8; off >= 1; off >>= 1)
                rmax = fmaxf(rmax, __shfl_xor_sync(0xffffffffu, rmax, off));
            mnew[i] = fmaxf(m_r[i], rmax);
            corr[i] = __expf(m_r[i] - mnew[i]);
            m_r[i] = mnew[i];
            float rs = 0.f;
#pragma unroll
            for (int j = 0; j < 4; j++) {
                float p = __expf(s[i][j] - mnew[i]);
                s[i][j] = p;
                rs += p;
            }
#pragma unroll
            for (int off = 8; off >= 1; off >>= 1)
                rs += __shfl_xor_sync(0xffffffffu, rs, off);
            l_r[i] = l_r[i] * corr[i] + rs;
            ull_t c2 = dup2(corr[i]);
            Oc2[i][0] = mul2(Oc2[i][0], c2);
            Oc2[i][1] = mul2(Oc2[i][1], c2);
        }

        __syncthreads();   // done reading Ks as K
        // store P duplicated (p,p) pairs into P2 [i][j]
#pragma unroll
        for (int i = 0; i < 4; i++) {
            int row = ty * 4 + i;
            P2[row][tx * 4 + 0] = dup2(s[i][0]);
            P2[row][tx * 4 + 1] = dup2(s[i][1]);
            P2[row][tx * 4 + 2] = dup2(s[i][2]);
            P2[row][tx * 4 + 3] = dup2(s[i][3]);
        }
        __syncthreads();

        // O += P V : packed along d-pairs (Vs[j][.] contiguous); P pre-dup'd
        for (int j = 0; j < 64; j++) {
            ulonglong2 v2 = *(const ulonglong2*)&Vs[j][tx * 4];
            ull_t p0 = P2[ty * 4 + 0][j];
            ull_t p1 = P2[ty * 4 + 1][j];
            ull_t p2 = P2[ty * 4 + 2][j];
            ull_t p3 = P2[ty * 4 + 3][j];
            Oc2[0][0] = fma2(p0, v2.x, Oc2[0][0]);
            Oc2[0][1] = fma2(p0, v2.y, Oc2[0][1]);
            Oc2[1][0] = fma2(p1, v2.x, Oc2[1][0]);
            Oc2[1][1] = fma2(p1, v2.y, Oc2[1][1]);
            Oc2[2][0] = fma2(p2, v2.x, Oc2[2][0]);
            Oc2[2][1] = fma2(p2, v2.y, Oc2[2][1]);
            Oc2[3][0] = fma2(p3, v2.x, Oc2[3][0]);
            Oc2[3][1] = fma2(p3, v2.y, Oc2[3][1]);
        }
    }

    // write O / l  ->  x in (B, N, H*hd) layout (fp32)
#pragma unroll
    for (int i = 0; i < 4; i++) {
        int row = qt * 64 + ty * 4 + i;
        float inv = 1.f / l_r[i];
        float v0, v1, v2, v3;
        unpack2(Oc2[i][0], v0, v1);
        unpack2(Oc2[i][1], v2, v3);
        float4 r;
        r.x = v0 * inv; r.y = v1 * inv; r.z = v2 * inv; r.w = v3 * inv;
        *(float4*)(o + ((long)(b * NN + row)) * DD + hoff + tx * 4) = r;
    }
}

// ---------------- launch ------------------------------------------------------
extern "C" void kernel_launch(void* const* d_in, const int* in_sizes, int n_in,
                              void* d_out, int out_size) {
    const float* in_q   = (const float*)d_in[0];
    const float* in_k   = (const float*)d_in[1];
    const float* in_v   = (const float*)d_in[2];
    const float* Wq     = (const float*)d_in[3];
    const float* Wk     = (const float*)d_in[4];
    const float* Wv     = (const float*)d_in[5];
    const float* Wproj  = (const float*)d_in[6];
    const float* bproj  = (const float*)d_in[7];
    const float* cpAtt  = (const float*)d_in[8];
    const float* cpC    = (const float*)d_in[9];
    const float* Uw     = (const float*)d_in[10];
    const float* Vw     = (const float*)d_in[11];
    float* out = (float*)d_out;

    float *dq, *dk, *dv, *dx, *dweff;
    cudaGetSymbolAddress((void**)&dq, d_q);
    cudaGetSymbolAddress((void**)&dk, d_k);
    cudaGetSymbolAddress((void**)&dv, d_v);
    cudaGetSymbolAddress((void**)&dx, d_x);
    cudaGetSymbolAddress((void**)&dweff, d_Weff);

    cudaFuncSetAttribute(attn_kernel,
                         cudaFuncAttributeMaxDynamicSharedMemorySize, ATTN_SMEM);

    // fold CP adapter into effective weights
    cpc_kernel<<<64, 256>>>(cpC, cpAtt);
    tmat_kernel<<<1024, 256>>>(Vw);
    weff_kernel<<<16384, 256>>>(Wq, Wk, Wv, Wproj, Uw);

    // q / k / v projections fused into ONE launch: z selects (A, B, C)
    dim3 ggrid3(1024 / 128, MTOT / 128, 3);
    sgemm3_kernel<<<ggrid3, 256>>>(in_q, in_k, in_v, dweff, nullptr, dq, dk, dv);

    // attention (fp32 packed-f32x2)
    attn_kernel<<<dim3(32, 16, 4), 256, ATTN_SMEM>>>(dq, dk, dv, dx);

    // output projection (+bias), with folded p_cp adapter (weights slot 3)
    dim3 pgrid(1024 / 128, MTOT / 128, 1);
    sgemm3_kernel<<<pgrid, 256>>>(dx, dx, dx, dweff + 3 * 1048576, bproj, out, out, out);
}

// round 16
// speedup vs baseline: 1.2076x; 1.2076x over previous
#include <cuda_runtime.h>
#include <cuda_bf16.h>
#include <math.h>
#include <stdint.h>

// Problem constants
#define BB 4
#define NN 2048
#define DD 1024
#define HH 16
#define HD 64
#define MTOT (BB*NN)          // 8192
#define ATT_SCALE 0.125f

// ---------------- scratch (static device memory) -----------------------------
__device__ float d_cpc[4 * 64 * 64];
__device__ float d_T[4 * 64 * 1024];
__device__ float d_Weff[4 * 1024 * 1024];       // fp32 folded weights [f][k][n]
__device__ float d_q[MTOT * DD];
__device__ float d_k[MTOT * DD];
__device__ float d_v[MTOT * DD];
// split-bf16 operands: slots 0..2 = q/k/v inputs, slot 3 = attention output x
__device__ __nv_bfloat16 d_Ahi[4][MTOT * DD];
__device__ __nv_bfloat16 d_Alo[4][MTOT * DD];
// transposed split weights: [f][n][k]
__device__ __nv_bfloat16 d_Whi[4][DD * DD];
__device__ __nv_bfloat16 d_Wlo[4][DD * DD];

// ---------------- helpers -----------------------------------------------------
typedef unsigned long long ull_t;

__device__ __forceinline__ ull_t fma2(ull_t a, ull_t b, ull_t c) {
    ull_t d;
    asm("fma.rn.f32x2 %0, %1, %2, %3;" : "=l"(d) : "l"(a), "l"(b), "l"(c));
    return d;
}
__device__ __forceinline__ ull_t mul2(ull_t a, ull_t b) {
    ull_t d;
    asm("mul.rn.f32x2 %0, %1, %2;" : "=l"(d) : "l"(a), "l"(b));
    return d;
}
__device__ __forceinline__ ull_t dup2(float x) {
    ull_t r;
    asm("mov.b64 %0, {%1, %1};" : "=l"(r) : "f"(x));
    return r;
}
__device__ __forceinline__ void unpack2(ull_t v, float& lo, float& hi) {
    asm("mov.b64 {%0, %1}, %2;" : "=f"(lo), "=f"(hi) : "l"(v));
}

__device__ __forceinline__ uint32_t smem_u32(const void* p) {
    uint32_t a;
    asm("{ .reg .u64 t; cvta.to.shared.u64 t, %1; cvt.u32.u64 %0, t; }"
        : "=r"(a) : "l"(p));
    return a;
}
__device__ __forceinline__ void ldsm4(uint32_t* r, uint32_t addr) {
    asm volatile("ldmatrix.sync.aligned.m8n8.x4.shared.b16 {%0,%1,%2,%3}, [%4];"
        : "=r"(r[0]), "=r"(r[1]), "=r"(r[2]), "=r"(r[3]) : "r"(addr));
}
__device__ __forceinline__ void ldsm2(uint32_t* r, uint32_t addr) {
    asm volatile("ldmatrix.sync.aligned.m8n8.x2.shared.b16 {%0,%1}, [%2];"
        : "=r"(r[0]), "=r"(r[1]) : "r"(addr));
}
__device__ __forceinline__ void mma16816(float* d, const uint32_t* a, const uint32_t* b) {
    asm volatile(
        "mma.sync.aligned.m16n8k16.row.col.f32.bf16.bf16.f32 "
        "{%0,%1,%2,%3}, {%4,%5,%6,%7}, {%8,%9}, {%0,%1,%2,%3};"
        : "+f"(d[0]), "+f"(d[1]), "+f"(d[2]), "+f"(d[3])
        : "r"(a[0]), "r"(a[1]), "r"(a[2]), "r"(a[3]), "r"(b[0]), "r"(b[1]));
}
__device__ __forceinline__ void cpasync16(uint32_t saddr, const void* gaddr) {
    asm volatile("cp.async.ca.shared.global [%0], [%1], 16;"
                 :: "r"(saddr), "l"(gaddr));
}

// ---------------- prep kernels -----------------------------------------------
__global__ void cpc_kernel(const float* __restrict__ cpC,
                           const float* __restrict__ cpAtt) {
    int idx = blockIdx.x * 256 + threadIdx.x;
    int f = idx >> 12;
    int rem = idx & 4095;
    const float* c = cpC + rem * 64;
    float s = 0.f;
#pragma unroll 8
    for (int r = 0; r < 64; r++) s += c[r] * cpAtt[r * 4 + f];
    d_cpc[f * 4096 + rem] = s;
}

__global__ void tmat_kernel(const float* __restrict__ Vw) {
    int idx = blockIdx.x * 256 + threadIdx.x;
    int f = idx >> 16;
    int rem = idx & 65535;
    int x = rem >> 10;
    int d = rem & 1023;
    const float* cp = d_cpc + f * 4096 + x * 64;
    float s = 0.f;
#pragma unroll 8
    for (int y = 0; y < 64; y++) s += cp[y] * Vw[y * 1024 + d];
    d_T[idx] = s;
}

__global__ void weff_kernel(const float* __restrict__ Wq, const float* __restrict__ Wk,
                            const float* __restrict__ Wv, const float* __restrict__ Wp,
                            const float* __restrict__ U) {
    int idx = blockIdx.x * 256 + threadIdx.x;
    int f = idx >> 20;
    int rem = idx & 1048575;
    int i = rem >> 10;
    int d = rem & 1023;
    const float* W = (f == 0) ? Wq : (f == 1) ? Wk : (f == 2) ? Wv : Wp;
    const float* Tf = d_T + f * 65536;
    const float* Ur = U + i * 64;
    float s = W[rem];
#pragma unroll 8
    for (int x = 0; x < 64; x++) s += Ur[x] * Tf[x * 1024 + d];
    d_Weff[idx] = s;
}

// transpose + split Weff[f][k][n] -> Whi/Wlo[f][n][k]
__global__ void wsplit_kernel() {
    __shared__ float t[32][33];
    int f = blockIdx.z;
    int n0 = blockIdx.x * 32, k0 = blockIdx.y * 32;
    for (int r = threadIdx.y; r < 32; r += 8)
        t[r][threadIdx.x] = d_Weff[f * 1048576 + (k0 + r) * 1024 + n0 + threadIdx.x];
    __syncthreads();
    for (int r = threadIdx.y; r < 32; r += 8) {
        float v = t[threadIdx.x][r];   // Weff[k0+tx][n0+r]
        int n = n0 + r, k = k0 + threadIdx.x;
        __nv_bfloat16 hi = __float2bfloat16(v);
        d_Whi[f][n * 1024 + k] = hi;
        d_Wlo[f][n * 1024 + k] = __float2bfloat16(v - __bfloat162float(hi));
    }
}

// split fp32 inputs into bf16 hi/lo (slots 0..2)
__global__ void split_kernel(const float* __restrict__ q, const float* __restrict__ k,
                             const float* __restrict__ v) {
    int z = blockIdx.z;
    const float* src = (z == 0) ? q : (z == 1) ? k : v;
    long i = ((long)blockIdx.x * 256 + threadIdx.x) * 4;
    float4 val = *(const float4*)(src + i);
    __nv_bfloat162 h0, h1, l0, l1;
    h0.x = __float2bfloat16(val.x); h0.y = __float2bfloat16(val.y);
    h1.x = __float2bfloat16(val.z); h1.y = __float2bfloat16(val.w);
    l0.x = __float2bfloat16(val.x - __bfloat162float(h0.x));
    l0.y = __float2bfloat16(val.y - __bfloat162float(h0.y));
    l1.x = __float2bfloat16(val.z - __bfloat162float(h1.x));
    l1.y = __float2bfloat16(val.w - __bfloat162float(h1.y));
    *(__nv_bfloat162*)(&d_Ahi[z][i])     = h0;
    *(__nv_bfloat162*)(&d_Ahi[z][i + 2]) = h1;
    *(__nv_bfloat162*)(&d_Alo[z][i])     = l0;
    *(__nv_bfloat162*)(&d_Alo[z][i + 2]) = l1;
}

// ---------------- mma.sync split-bf16 GEMM ------------------------------------
// C[M x 1024] = A @ W^T via Ahi*Whi + Ahi*Wlo + Alo*Whi  (HMMA, fp32 accum)
// CTA tile 128x128, K-slab 32, cp.async double-buffer (2 x 32KB).
// Warp (8 total): mw = w&1 (64 rows), nw = w>>1 (32 cols); 4x4 m16n8 tiles.
// SMEM stage: Ahi@0 Alo@8K Bhi@16K Blo@24K; rows 64B (32 bf16), XOR-4 swizzle.
#define GEMM_SMEM 65536

__global__ void __launch_bounds__(256, 2)
mma_gemm_kernel(int abase, int wbase, const float* __restrict__ bias,
                float* __restrict__ C0, float* __restrict__ C1,
                float* __restrict__ C2) {
    extern __shared__ char gsm[];
    uint32_t sb = smem_u32(gsm);
    int tid = threadIdx.x, lane = tid & 31, w = tid >> 5;
    int mw = w & 1, nw = w >> 1;
    int z = blockIdx.z;
    const __nv_bfloat16* Ah = d_Ahi[abase + z];
    const __nv_bfloat16* Al = d_Alo[abase + z];
    const __nv_bfloat16* Wh = d_Whi[wbase + z];
    const __nv_bfloat16* Wl = d_Wlo[wbase + z];
    float* C = (z == 0) ? C0 : (z == 1) ? C1 : C2;
    int bx = blockIdx.x * 128;   // N offset
    int my = blockIdx.y * 128;   // M offset

    float acc[4][4][4];
#pragma unroll
    for (int mt = 0; mt < 4; mt++)
#pragma unroll
        for (int nt = 0; nt < 4; nt++)
#pragma unroll
            for (int r = 0; r < 4; r++) acc[mt][nt][r] = 0.f;

    // cp.async: 512 16B-chunks per 128x32 array; 2 chunks/thread/array
    auto load_slab = [&](int s, int st) {
        uint32_t base = sb + st * 32768;
#pragma unroll
        for (int j = 0; j < 2; j++) {
            int cid = tid * 2 + j;
            int row = cid >> 2, x = cid & 3;
            uint32_t soff = row * 64 + ((x ^ (row & 3)) << 4);
            long ga = (long)(my + row) * 1024 + s * 32 + x * 8;
            long gw = (long)(bx + row) * 1024 + s * 32 + x * 8;
            cpasync16(base + soff,         Ah + ga);
            cpasync16(base + 8192 + soff,  Al + ga);
            cpasync16(base + 16384 + soff, Wh + gw);
            cpasync16(base + 24576 + soff, Wl + gw);
        }
        asm volatile("cp.async.commit_group;");
    };

    // fragment smem addresses (ldmatrix, swizzled)
    auto a_addr = [&](uint32_t base, int mt, int ks) {
        int row = mw * 64 + mt * 16 + (lane & 15);
        int x = ks * 2 + (lane >> 4);
        return base + row * 64 + ((x ^ (row & 3)) << 4);
    };
    auto b_addr = [&](uint32_t base, int nt, int ks) {
        int row = nw * 32 + nt * 8 + (lane & 7);
        int x = ks * 2 + ((lane >> 3) & 1);
        return base + row * 64 + ((x ^ (row & 3)) << 4);
    };

    load_slab(0, 0);

    for (int s = 0; s < 32; s++) {
        int st = s & 1;
        if (s + 1 < 32) {
            load_slab(s + 1, st ^ 1);
            asm volatile("cp.async.wait_group 1;");
        } else {
            asm volatile("cp.async.wait_group 0;");
        }
        __syncthreads();

        uint32_t base = sb + st * 32768;
#pragma unroll
        for (int ks = 0; ks < 2; ks++) {
            uint32_t afr[4][4], bfr[4][2];
            // hi * hi
#pragma unroll
            for (int mt = 0; mt < 4; mt++) ldsm4(afr[mt], a_addr(base, mt, ks));
#pragma unroll
            for (int nt = 0; nt < 4; nt++) ldsm2(bfr[nt], b_addr(base + 16384, nt, ks));
#pragma unroll
            for (int mt = 0; mt < 4; mt++)
#pragma unroll
                for (int nt = 0; nt < 4; nt++) mma16816(acc[mt][nt], afr[mt], bfr[nt]);
            // hi * lo
#pragma unroll
            for (int nt = 0; nt < 4; nt++) ldsm2(bfr[nt], b_addr(base + 24576, nt, ks));
#pragma unroll
            for (int mt = 0; mt < 4; mt++)
#pragma unroll
                for (int nt = 0; nt < 4; nt++) mma16816(acc[mt][nt], afr[mt], bfr[nt]);
            // lo * hi
#pragma unroll
            for (int mt = 0; mt < 4; mt++) ldsm4(afr[mt], a_addr(base + 8192, mt, ks));
#pragma unroll
            for (int nt = 0; nt < 4; nt++) ldsm2(bfr[nt], b_addr(base + 16384, nt, ks));
#pragma unroll
            for (int mt = 0; mt < 4; mt++)
#pragma unroll
                for (int nt = 0; nt < 4; nt++) mma16816(acc[mt][nt], afr[mt], bfr[nt]);
        }
        __syncthreads();
    }

    // epilogue: d0,d1 -> (row g, col c,c+1); d2,d3 -> (row g+8)
    int g = lane >> 2, cl = (lane & 3) * 2;
#pragma unroll
    for (int mt = 0; mt < 4; mt++) {
#pragma unroll
        for (int nt = 0; nt < 4; nt++) {
            int row = my + mw * 64 + mt * 16 + g;
            int col = bx + nw * 32 + nt * 8 + cl;
            float b0 = 0.f, b1 = 0.f;
            if (bias) { b0 = bias[col]; b1 = bias[col + 1]; }
            float2 v0 = { acc[mt][nt][0] + b0, acc[mt][nt][1] + b1 };
            float2 v1 = { acc[mt][nt][2] + b0, acc[mt][nt][3] + b1 };
            *(float2*)(C + (long)row * 1024 + col)       = v0;
            *(float2*)(C + (long)(row + 8) * 1024 + col) = v1;
        }
    }
}

// ---------------- flash attention (prefetch + f32x2; writes split-bf16 x) -----
// dyn smem 80KB: Qs@0 | Ks@16K | Vs@32K | P2@48K (32K)
#define ATTN_SMEM 81920

__global__ void __launch_bounds__(256, 2)
attn_kernel(const float* __restrict__ q, const float* __restrict__ k,
            const float* __restrict__ v) {
    extern __shared__ char asmem[];
    float (*Qs)[64] = (float(*)[64])(asmem);
    float (*Ks)[64] = (float(*)[64])(asmem + 16384);
    float (*Vs)[64] = (float(*)[64])(asmem + 32768);
    ull_t (*P2)[64] = (ull_t(*)[64])(asmem + 49152);

    int b = blockIdx.z, h = blockIdx.y, qt = blockIdx.x;
    int tid = threadIdx.x;
    int tx = tid & 15, ty = tid >> 4;

    const long hoff = (long)h * HD;
    const float* qbase = q + ((long)(b * NN + qt * 64)) * DD + hoff;
    const float* kbase = k + ((long)b * NN) * DD + hoff;
    const float* vbase = v + ((long)b * NN) * DD + hoff;

    const int si = tid >> 4;
    const int sd4 = (tid & 15) << 2;

#pragma unroll
    for (int it = 0; it < 4; it++) {
        int i = si + 16 * it;
        float4 val = *(const float4*)(qbase + (long)i * DD + sd4);
        Qs[sd4 + 0][i] = val.x * ATT_SCALE;
        Qs[sd4 + 1][i] = val.y * ATT_SCALE;
        Qs[sd4 + 2][i] = val.z * ATT_SCALE;
        Qs[sd4 + 3][i] = val.w * ATT_SCALE;
    }

    float m_r[4], l_r[4];
    ull_t Oc2[4][2];
#pragma unroll
    for (int i = 0; i < 4; i++) {
        m_r[i] = -1e30f; l_r[i] = 0.f;
        Oc2[i][0] = 0ull; Oc2[i][1] = 0ull;
    }

    float4 kreg[4], vreg[4];
#pragma unroll
    for (int it = 0; it < 4; it++) {
        int i = si + 16 * it;
        kreg[it] = *(const float4*)(kbase + (long)i * DD + sd4);
        vreg[it] = *(const float4*)(vbase + (long)i * DD + sd4);
    }

    for (int kt = 0; kt < 32; kt++) {
        __syncthreads();   // S1
#pragma unroll
        for (int it = 0; it < 4; it++) {
            int i = si + 16 * it;
            Ks[sd4 + 0][i] = kreg[it].x; Ks[sd4 + 1][i] = kreg[it].y;
            Ks[sd4 + 2][i] = kreg[it].z; Ks[sd4 + 3][i] = kreg[it].w;
            *(float4*)&Vs[i][sd4] = vreg[it];
        }
        __syncthreads();   // S2

        if (kt + 1 < 32) {
            const float* kb = kbase + (long)(kt + 1) * 64 * DD;
            const float* vb = vbase + (long)(kt + 1) * 64 * DD;
#pragma unroll
            for (int it = 0; it < 4; it++) {
                int i = si + 16 * it;
                kreg[it] = *(const float4*)(kb + (long)i * DD + sd4);
                vreg[it] = *(const float4*)(vb + (long)i * DD + sd4);
            }
        }

        ull_t s2[2][4];
#pragma unroll
        for (int ip = 0; ip < 2; ip++)
#pragma unroll
            for (int j = 0; j < 4; j++) s2[ip][j] = 0ull;

        for (int d = 0; d < 64; d++) {
            ulonglong2 a2 = *(const ulonglong2*)&Qs[d][ty * 4];
            float4 bk = *(const float4*)&Ks[d][tx * 4];
            ull_t b0 = dup2(bk.x), b1 = dup2(bk.y);
            ull_t b2 = dup2(bk.z), b3 = dup2(bk.w);
            s2[0][0] = fma2(a2.x, b0, s2[0][0]);
            s2[0][1] = fma2(a2.x, b1, s2[0][1]);
            s2[0][2] = fma2(a2.x, b2, s2[0][2]);
            s2[0][3] = fma2(a2.x, b3, s2[0][3]);
            s2[1][0] = fma2(a2.y, b0, s2[1][0]);
            s2[1][1] = fma2(a2.y, b1, s2[1][1]);
            s2[1][2] = fma2(a2.y, b2, s2[1][2]);
            s2[1][3] = fma2(a2.y, b3, s2[1][3]);
        }

        float s[4][4];
#pragma unroll
        for (int j = 0; j < 4; j++) {
            unpack2(s2[0][j], s[0][j], s[1][j]);
            unpack2(s2[1][j], s[2][j], s[3][j]);
        }

        float mnew[4], corr[4];
#pragma unroll
        for (int i = 0; i < 4; i++) {
            float rmax = fmaxf(fmaxf(s[i][0], s[i][1]), fmaxf(s[i][2], s[i][3]));
#pragma unroll
            for (int off = 8; off >= 1; off >>= 1)
                rmax = fmaxf(rmax, __shfl_xor_sync(0xffffffffu, rmax, off));
            mnew[i] = fmaxf(m_r[i], rmax);
            corr[i] = __expf(m_r[i] - mnew[i]);
            m_r[i] = mnew[i];
            float rs = 0.f;
#pragma unroll
            for (int j = 0; j < 4; j++) {
                float p = __expf(s[i][j] - mnew[i]);
                s[i][j] = p;
                rs += p;
            }
#pragma unroll
            for (int off = 8; off >= 1; off >>= 1)
                rs += __shfl_xor_sync(0xffffffffu, rs, off);
            l_r[i] = l_r[i] * corr[i] + rs;
            ull_t c2 = dup2(corr[i]);
            Oc2[i][0] = mul2(Oc2[i][0], c2);
            Oc2[i][1] = mul2(Oc2[i][1], c2);
        }

#pragma unroll
        for (int i = 0; i < 4; i++) {
            int row = ty * 4 + i;
            P2[row][tx * 4 + 0] = dup2(s[i][0]);
            P2[row][tx * 4 + 1] = dup2(s[i][1]);
            P2[row][tx * 4 + 2] = dup2(s[i][2]);
            P2[row][tx * 4 + 3] = dup2(s[i][3]);
        }
        __syncthreads();   // S3

        for (int j = 0; j < 64; j++) {
            ulonglong2 v2 = *(const ulonglong2*)&Vs[j][tx * 4];
            ull_t p0 = P2[ty * 4 + 0][j];
            ull_t p1 = P2[ty * 4 + 1][j];
            ull_t p2 = P2[ty * 4 + 2][j];
            ull_t p3 = P2[ty * 4 + 3][j];
            Oc2[0][0] = fma2(p0, v2.x, Oc2[0][0]);
            Oc2[0][1] = fma2(p0, v2.y, Oc2[0][1]);
            Oc2[1][0] = fma2(p1, v2.x, Oc2[1][0]);
            Oc2[1][1] = fma2(p1, v2.y, Oc2[1][1]);
            Oc2[2][0] = fma2(p2, v2.x, Oc2[2][0]);
            Oc2[2][1] = fma2(p2, v2.y, Oc2[2][1]);
            Oc2[3][0] = fma2(p3, v2.x, Oc2[3][0]);
            Oc2[3][1] = fma2(p3, v2.y, Oc2[3][1]);
        }
    }

    // write x as split-bf16 (slot 3) for the proj mma_gemm
    __nv_bfloat16* xh = d_Ahi[3];
    __nv_bfloat16* xl = d_Alo[3];
#pragma unroll
    for (int i = 0; i < 4; i++) {
        int row = qt * 64 + ty * 4 + i;
        float inv = 1.f / l_r[i];
        long base = ((long)(b * NN + row)) * DD + hoff + tx * 4;
        float v0, v1, v2, v3;
        unpack2(Oc2[i][0], v0, v1);
        unpack2(Oc2[i][1], v2, v3);
        v0 *= inv; v1 *= inv; v2 *= inv; v3 *= inv;
        __nv_bfloat162 h0, h1, l0, l1;
        h0.x = __float2bfloat16(v0); h0.y = __float2bfloat16(v1);
        h1.x = __float2bfloat16(v2); h1.y = __float2bfloat16(v3);
        l0.x = __float2bfloat16(v0 - __bfloat162float(h0.x));
        l0.y = __float2bfloat16(v1 - __bfloat162float(h0.y));
        l1.x = __float2bfloat16(v2 - __bfloat162float(h1.x));
        l1.y = __float2bfloat16(v3 - __bfloat162float(h1.y));
        *(__nv_bfloat162*)(xh + base)     = h0;
        *(__nv_bfloat162*)(xh + base + 2) = h1;
        *(__nv_bfloat162*)(xl + base)     = l0;
        *(__nv_bfloat162*)(xl + base + 2) = l1;
    }
}

// ---------------- launch ------------------------------------------------------
extern "C" void kernel_launch(void* const* d_in, const int* in_sizes, int n_in,
                              void* d_out, int out_size) {
    const float* in_q   = (const float*)d_in[0];
    const float* in_k   = (const float*)d_in[1];
    const float* in_v   = (const float*)d_in[2];
    const float* Wq     = (const float*)d_in[3];
    const float* Wk     = (const float*)d_in[4];
    const float* Wv     = (const float*)d_in[5];
    const float* Wproj  = (const float*)d_in[6];
    const float* bproj  = (const float*)d_in[7];
    const float* cpAtt  = (const float*)d_in[8];
    const float* cpC    = (const float*)d_in[9];
    const float* Uw     = (const float*)d_in[10];
    const float* Vw     = (const float*)d_in[11];
    float* out = (float*)d_out;

    float *dq, *dk, *dv;
    cudaGetSymbolAddress((void**)&dq, d_q);
    cudaGetSymbolAddress((void**)&dk, d_k);
    cudaGetSymbolAddress((void**)&dv, d_v);

    cudaFuncSetAttribute(mma_gemm_kernel,
                         cudaFuncAttributeMaxDynamicSharedMemorySize, GEMM_SMEM);
    cudaFuncSetAttribute(attn_kernel,
                         cudaFuncAttributeMaxDynamicSharedMemorySize, ATTN_SMEM);

    // fold CP adapter; build split operands
    cpc_kernel<<<64, 256>>>(cpC, cpAtt);
    tmat_kernel<<<1024, 256>>>(Vw);
    weff_kernel<<<16384, 256>>>(Wq, Wk, Wv, Wproj, Uw);
    wsplit_kernel<<<dim3(32, 32, 4), dim3(32, 8)>>>();
    split_kernel<<<dim3(8192, 1, 3), 256>>>(in_q, in_k, in_v);

    // q/k/v projections on HMMA tensor cores (one launch, z selects operands)
    mma_gemm_kernel<<<dim3(8, 64, 3), 256, GEMM_SMEM>>>(0, 0, nullptr, dq, dk, dv);

    // attention (register-prefetched, 3-sync, f32x2; writes split-bf16 x)
    attn_kernel<<<dim3(32, 16, 4), 256, ATTN_SMEM>>>(dq, dk, dv);

    // output projection (+bias)
    mma_gemm_kernel<<<dim3(8, 64, 1), 256, GEMM_SMEM>>>(3, 3, bproj, out, out, out);
}